// round 3
// baseline (speedup 1.0000x reference)
#include <cuda_runtime.h>
#include <math.h>

// FraudDetectionHybridModel — closed-form quantum-circuit reduction.
// feats(patch) = prefix products of cos(pixel); RZ(patch_params) is pure phase (unused).
// out[b] = sigmoid( cos( sum_{p,w} feats[b,p,w] * W[p*4+w] ) )
//
// Structure: CTA = 256 threads = 8 warps = 8 images.
//  Phase 1: stage 8 images (25088 B) + weights (3136 B) to smem with
//           CTA-wide contiguous float4 loads (perfect 512B/warp coalescing, MLP~7).
//  Phase 2: warp w reduces image w from smem; lane owns whole patches via LDS.

#define THREADS 256
#define IMGS_PER_CTA 8

__device__ __forceinline__ float patch_contrib(const float* __restrict__ im,
                                               const float* __restrict__ sw,
                                               int p)
{
    const int i = p / 14;
    const int j = p - i * 14;
    const float2 tp = *reinterpret_cast<const float2*>(im + i * 56 + 2 * j);
    const float2 bt = *reinterpret_cast<const float2*>(im + i * 56 + 28 + 2 * j);
    const float4 wv = *reinterpret_cast<const float4*>(sw + 4 * p);

    const float c0 = __cosf(tp.x), c1 = __cosf(tp.y);
    const float c2 = __cosf(bt.x), c3 = __cosf(bt.y);
    const float f0 = c0, f1 = f0 * c1, f2 = f1 * c2, f3 = f2 * c3;
    return fmaf(f0, wv.x, fmaf(f1, wv.y, fmaf(f2, wv.z, f3 * wv.w)));
}

__global__ void __launch_bounds__(THREADS)
fraud_kernel(const float* __restrict__ x,   // [B, 784]
             const float* __restrict__ w,   // [785]
             float* __restrict__ out,       // [B]
             int B)
{
    __shared__ float simg[IMGS_PER_CTA * 784];   // 25088 B
    __shared__ float sw[784];                    //  3136 B

    const int tid  = threadIdx.x;
    const int warp = tid >> 5;
    const int lane = tid & 31;

    int img0 = blockIdx.x * IMGS_PER_CTA;
    if (img0 + IMGS_PER_CTA > B) img0 = B - IMGS_PER_CTA;   // B >= 8; duplicate work is safe

    // ---- Phase 1: coalesced staging (1568 float4 of pixels + 196 float4 of weights) ----
    const float4* gx = reinterpret_cast<const float4*>(x + (size_t)img0 * 784);
    float4* s4 = reinterpret_cast<float4*>(simg);
    #pragma unroll
    for (int k = 0; k < 6; ++k)
        s4[tid + k * THREADS] = gx[tid + k * THREADS];
    if (tid < 32)
        s4[1536 + tid] = gx[1536 + tid];
    if (tid < 196)
        reinterpret_cast<float4*>(sw)[tid] = reinterpret_cast<const float4*>(w)[tid];
    __syncthreads();

    // ---- Phase 2: warp reduces its image ----
    const float* im = simg + warp * 784;
    float acc = 0.0f;
    #pragma unroll
    for (int t = 0; t < 6; ++t)
        acc += patch_contrib(im, sw, lane + 32 * t);     // p in [0,192)
    if (lane < 4)
        acc += patch_contrib(im, sw, 192 + lane);        // p in [192,196)

    #pragma unroll
    for (int off = 16; off > 0; off >>= 1)
        acc += __shfl_xor_sync(0xffffffffu, acc, off);

    if (lane == 0) {
        const int img = img0 + warp;
        if (img < B) {
            const float cv = cosf(acc);                  // |acc| can be ~40: accurate cos
            out[img] = 1.0f / (1.0f + __expf(-cv));
        }
    }
}

extern "C" void kernel_launch(void* const* d_in, const int* in_sizes, int n_in,
                              void* d_out, int out_size)
{
    const float* x = (const float*)d_in[0];   // [B,1,28,28]
    // d_in[1] = patch_params — provably unused (RZ is pure phase)
    const float* w = (const float*)d_in[2];   // [785]
    float* out = (float*)d_out;

    const int B = in_sizes[0] / 784;
    const int grid = (B + IMGS_PER_CTA - 1) / IMGS_PER_CTA;
    fraud_kernel<<<grid, THREADS>>>(x, w, out, B);
}